// round 7
// baseline (speedup 1.0000x reference)
#include <cuda_runtime.h>

// PrototypeField: B=262144, D=256, C=128.
// out[0] = 0.1*(1 - mean cos_sim), out[1..32768] = new_v (C,D).
//
// Identity: sum_i <dirs_n_i, new_v[label_i]> = sum_c <sums_c, new_v_c>,
// so dirs is read exactly once (268 MB, HBM floor ~34us).
//
// accum_kernel (148 CTAs x 512 thr, 16 warps x 8 classes/warp):
//   phase A: ballot counting-sort of the CTA's label slice into per-class
//   row lists (smem).
//   phase B: flat walk of the warp's sorted range with a DEPTH-4 register
//   pipeline (8 LDG.128 in flight/warp = 4KB; 64KB/SM) to cover memory
//   latency; register accumulators flushed to per-CTA partials with plain
//   STG.128 at class boundaries. No atomics, no persistent state to zero.
// class_kernel (128x256): per class, reduce 148 partials + EMA + renorm +
// write new_v + dot.  loss_kernel: sum per-class dots -> out[0].

#define DD 256
#define CC 128
#define GRID1 148
#define T1 512
#define NW (T1 / 32)          // 16 warps
#define CPW (CC / NW)         // 8 classes per warp
#define FULLM 0xFFFFFFFFu
#define MAXROWS 1792

__device__ float g_part[GRID1 * CC * DD];   // fully overwritten each run
__device__ float g_pcnt[GRID1 * CC];        // fully overwritten each run
__device__ float g_dots[CC];                // fully overwritten each run

#define DOT8(p, q) ((p).x*(p).x + (p).y*(p).y + (p).z*(p).z + (p).w*(p).w \
                  + (q).x*(q).x + (q).y*(q).y + (q).z*(q).z + (q).w*(q).w)
#define AXPY4(acc, v, s) do { (acc).x += (v).x*(s); (acc).y += (v).y*(s); \
                              (acc).z += (v).z*(s); (acc).w += (v).w*(s); } while (0)

__global__ __launch_bounds__(T1, 1) void accum_kernel(
    const float* __restrict__ dirs,
    const int* __restrict__ labels,
    int B)
{
    __shared__ int labs[MAXROWS];
    __shared__ unsigned short list[MAXROWS];
    __shared__ int ccount[CC];
    __shared__ int cbase[CC + 1];

    const int tid  = threadIdx.x;
    const int wid  = tid >> 5;            // warp owns classes [8w, 8w+8)
    const int lane = tid & 31;
    const int base_c = wid * CPW;

    const int rows_per = (B + GRID1 - 1) / GRID1;   // 1772
    const int row0  = blockIdx.x * rows_per;
    const int nrows = min(rows_per, B - row0);
    if (nrows <= 0) return;

    for (int i = tid; i < nrows; i += T1) labs[i] = labels[row0 + i];
    __syncthreads();

    // ---- Phase A1: per-class counts ----
    {
        int cnt[CPW];
        #pragma unroll
        for (int k = 0; k < CPW; k++) cnt[k] = 0;
        for (int b = 0; b < nrows; b += 32) {
            int r = b + lane;
            int lab = (r < nrows) ? labs[r] : -1;
            #pragma unroll
            for (int k = 0; k < CPW; k++)
                cnt[k] += __popc(__ballot_sync(FULLM, lab == base_c + k));
        }
        if (lane == 0) {
            #pragma unroll
            for (int k = 0; k < CPW; k++) ccount[base_c + k] = cnt[k];
        }
    }
    __syncthreads();

    // ---- Phase A2: exclusive prefix over 128 class counts (warp 0) ----
    if (wid == 0) {
        int k0 = ccount[lane * 4], k1 = ccount[lane * 4 + 1];
        int k2 = ccount[lane * 4 + 2], k3 = ccount[lane * 4 + 3];
        int s = k0 + k1 + k2 + k3;
        int x = s;
        #pragma unroll
        for (int o = 1; o < 32; o <<= 1) {
            int y = __shfl_up_sync(FULLM, x, o);
            if (lane >= o) x += y;
        }
        int excl = x - s;
        cbase[lane * 4]     = excl;
        cbase[lane * 4 + 1] = excl + k0;
        cbase[lane * 4 + 2] = excl + k0 + k1;
        cbase[lane * 4 + 3] = excl + k0 + k1 + k2;
        if (lane == 31) cbase[CC] = excl + s;
    }
    __syncthreads();

    // ---- Phase A3: fill class-sorted row lists ----
    {
        int off[CPW];
        #pragma unroll
        for (int k = 0; k < CPW; k++) off[k] = cbase[base_c + k];
        unsigned below = (1u << lane) - 1u;
        for (int b = 0; b < nrows; b += 32) {
            int r = b + lane;
            int lab = (r < nrows) ? labs[r] : -1;
            #pragma unroll
            for (int k = 0; k < CPW; k++) {
                unsigned m = __ballot_sync(FULLM, lab == base_c + k);
                if (lab == base_c + k)
                    list[off[k] + __popc(m & below)] = (unsigned short)r;
                off[k] += __popc(m);
            }
        }
    }
    __syncthreads();

    // ---- per-(cta,class) counts + zero partials of empty classes ----
    float* part_cta = g_part + blockIdx.x * (CC * DD);
    const float4 z = make_float4(0.f, 0.f, 0.f, 0.f);
    if (lane < CPW) {
        int c = base_c + lane;
        g_pcnt[blockIdx.x * CC + c] = (float)(cbase[c + 1] - cbase[c]);
    }
    #pragma unroll
    for (int k = 0; k < CPW; k++) {
        int c = base_c + k;
        if (cbase[c + 1] == cbase[c]) {
            float* pp = part_cta + c * DD + (lane << 2);
            *(float4*)pp = z;
            *(float4*)(pp + 128) = z;
        }
    }

    // ---- Phase B: flat walk, depth-4 register pipeline ----
    const int s0 = cbase[base_c], e0 = cbase[base_c + CPW];
    if (s0 < e0) {
        const float4* dbase = (const float4*)dirs + (long long)row0 * (DD / 4);
        int cls = base_c;
        while (s0 >= cbase[cls + 1]) cls++;

        float4 AL = z, AH = z;

        // preload rows s0 .. s0+3
        float4 a0 = z, a1 = z, b0 = z, b1 = z, c0 = z, c1 = z, d0 = z, d1 = z;
        {
            const float4* p = dbase + (long long)list[s0] * 64;
            a0 = __ldg(p + lane); a1 = __ldg(p + lane + 32);
        }
        if (s0 + 1 < e0) {
            const float4* p = dbase + (long long)list[s0 + 1] * 64;
            b0 = __ldg(p + lane); b1 = __ldg(p + lane + 32);
        }
        if (s0 + 2 < e0) {
            const float4* p = dbase + (long long)list[s0 + 2] * 64;
            c0 = __ldg(p + lane); c1 = __ldg(p + lane + 32);
        }
        if (s0 + 3 < e0) {
            const float4* p = dbase + (long long)list[s0 + 3] * 64;
            d0 = __ldg(p + lane); d1 = __ldg(p + lane + 32);
        }

        #pragma unroll 4
        for (int i = s0; i < e0; i++) {
            // prefetch row i+4
            float4 n0 = z, n1 = z;
            if (i + 4 < e0) {
                const float4* q = dbase + (long long)list[i + 4] * 64;
                n0 = __ldg(q + lane);
                n1 = __ldg(q + lane + 32);
            }

            // process row i (in a0,a1)
            float ss = DOT8(a0, a1);
            #pragma unroll
            for (int o = 16; o > 0; o >>= 1) ss += __shfl_xor_sync(FULLM, ss, o);
            float inv = 1.0f / fmaxf(sqrtf(ss), 1e-12f);
            AXPY4(AL, a0, inv);
            AXPY4(AH, a1, inv);

            if (i + 1 >= cbase[cls + 1]) {   // last row of class cls
                float* pp = part_cta + cls * DD + (lane << 2);
                *(float4*)pp = AL;
                *(float4*)(pp + 128) = AH;
                AL = z; AH = z;
                if (i + 1 < e0) {
                    cls++;
                    while (i + 1 >= cbase[cls + 1]) cls++;
                }
            }

            // rotate pipeline
            a0 = b0; a1 = b1;
            b0 = c0; b1 = c1;
            c0 = d0; c1 = d1;
            d0 = n0; d1 = n1;
        }
    }
}

__device__ __forceinline__ float block_sum256(float v, volatile float* red, int t)
{
    #pragma unroll
    for (int o = 16; o > 0; o >>= 1) v += __shfl_xor_sync(FULLM, v, o);
    __syncthreads();                 // protect red from previous use
    if ((t & 31) == 0) red[t >> 5] = v;
    __syncthreads();
    return red[0] + red[1] + red[2] + red[3] + red[4] + red[5] + red[6] + red[7];
}

__global__ __launch_bounds__(256, 4) void class_kernel(
    const float* __restrict__ v_class,
    const int* __restrict__ step_ptr,
    float* __restrict__ out,
    float Bf)
{
    __shared__ float red[8];
    const int c = blockIdx.x;
    const int t = threadIdx.x;       // dim index, 0..255

    // ---- reduce 148 partials (coalesced, unroll-4 for MLP) ----
    const float* pb = g_part + c * DD + t;
    float sA = 0.f, sB = 0.f, sC = 0.f, sD = 0.f;
    int j = 0;
    for (; j + 4 <= GRID1; j += 4) {
        sA += pb[(j + 0) * (CC * DD)];
        sB += pb[(j + 1) * (CC * DD)];
        sC += pb[(j + 2) * (CC * DD)];
        sD += pb[(j + 3) * (CC * DD)];
    }
    for (; j < GRID1; j++) sA += pb[j * (CC * DD)];
    float s = (sA + sB) + (sC + sD);          // sums_c[t]

    float cv = (t < GRID1) ? g_pcnt[t * CC + c] : 0.f;
    float cnt = block_sum256(cv, red, t);

    float stepf = (float)(*step_ptr);
    float alpha = fminf(0.02f, stepf / (stepf + 50.0f));
    float oma = 1.0f - alpha;

    float invc = 1.0f / fmaxf(cnt, 1.0f);
    float bm = s * invc;

    float nb = block_sum256(bm * bm, red, t);
    float invb = 1.0f / fmaxf(sqrtf(nb), 1e-12f);

    float vc = v_class[c * DD + t];
    float u = oma * vc + alpha * bm * invb;

    float nu = block_sum256(u * u, red, t);
    float invu = 1.0f / fmaxf(sqrtf(nu), 1e-12f);

    float w = (cnt > 0.0f) ? u * invu : vc;
    out[1 + c * DD + t] = w;

    float dot = block_sum256(s * w, red, t);
    if (t == 0) g_dots[c] = dot;
}

__global__ void loss_kernel(float* __restrict__ out, float Bf)
{
    __shared__ float red[4];
    const int t = threadIdx.x;       // 0..127
    float v = g_dots[t];
    #pragma unroll
    for (int o = 16; o > 0; o >>= 1) v += __shfl_xor_sync(FULLM, v, o);
    if ((t & 31) == 0) red[t >> 5] = v;
    __syncthreads();
    if (t == 0)
        out[0] = 0.1f * (1.0f - (red[0] + red[1] + red[2] + red[3]) / Bf);
}

extern "C" void kernel_launch(void* const* d_in, const int* in_sizes, int n_in,
                              void* d_out, int out_size)
{
    const float* dirs    = (const float*)d_in[0];
    const float* v_class = (const float*)d_in[1];
    const int*   labels  = (const int*)d_in[2];
    const int*   step    = (const int*)d_in[3];
    int B = in_sizes[2];

    accum_kernel<<<GRID1, T1>>>(dirs, labels, B);
    class_kernel<<<CC, 256>>>(v_class, step, (float*)d_out, (float)B);
    loss_kernel<<<1, 128>>>((float*)d_out, (float)B);
}

// round 8
// speedup vs baseline: 1.0682x; 1.0682x over previous
#include <cuda_runtime.h>
#include <cstdint>

// PrototypeField: B=262144, D=256, C=128.
// out[0] = 0.1*(1 - mean cos_sim), out[1..32768] = new_v (C,D).
//
// Identity: sum_i <dirs_n_i, new_v[label_i]> = sum_c <sums_c, new_v_c>,
// so dirs is read exactly once (268 MB, HBM floor ~34us).
//
// accum_kernel (148 CTAs x 512 thr, 16 warps x 8 classes/warp):
//   phase A: ballot counting-sort of the CTA's label slice into per-class
//   row lists (smem).
//   phase B: each warp streams its class-sorted rows through a private
//   8-slot x 1KB smem ring via cp.async (LDGSTS: no register dest, no
//   scoreboard slot -> true depth-6 pipeline, 96KB in flight/SM), consumes
//   rows with LDS.128 + warp allreduce, flushes register accumulators to
//   per-CTA partials with plain STG.128 at class boundaries. No atomics,
//   no persistent state to zero.
// class_kernel (128x256): per class, reduce 148 partials + EMA + renorm +
// write new_v + dot.  loss_kernel: sum per-class dots -> out[0].

#define DD 256
#define CC 128
#define GRID1 148
#define T1 512
#define NW (T1 / 32)          // 16 warps
#define CPW (CC / NW)         // 8 classes per warp
#define FULLM 0xFFFFFFFFu
#define MAXROWS 1792
#define DEPTH 8               // ring slots per warp (power of 2)
#define PEND 6                // cp.async groups kept in flight

// dynamic smem layout (bytes):
//   [0, 131072)           stage: 16 warps x 8 slots x 1024B
//   [131072, 134656)      labs   short[1792]
//   [134656, 138240)      list   ushort[1792]
//   [138240, 138752)      ccount int[128]
//   [138752, 139268)      cbase  int[129]
#define OFF_STAGE  0
#define OFF_LABS   131072
#define OFF_LIST   134656
#define OFF_CCOUNT 138240
#define OFF_CBASE  138752
#define SMEM_BYTES 139280

__device__ float g_part[GRID1 * CC * DD];   // fully overwritten each run
__device__ float g_pcnt[GRID1 * CC];        // fully overwritten each run
__device__ float g_dots[CC];                // fully overwritten each run

#define DOT8(p, q) ((p).x*(p).x + (p).y*(p).y + (p).z*(p).z + (p).w*(p).w \
                  + (q).x*(q).x + (q).y*(q).y + (q).z*(q).z + (q).w*(q).w)
#define AXPY4(acc, v, s) do { (acc).x += (v).x*(s); (acc).y += (v).y*(s); \
                              (acc).z += (v).z*(s); (acc).w += (v).w*(s); } while (0)

__device__ __forceinline__ void cp16(uint32_t dst, const void* src) {
    asm volatile("cp.async.cg.shared.global [%0], [%1], 16;\n"
                 :: "r"(dst), "l"(src) : "memory");
}

__global__ __launch_bounds__(T1, 1) void accum_kernel(
    const float* __restrict__ dirs,
    const int* __restrict__ labels,
    int B)
{
    extern __shared__ char dynsmem[];
    short*          labs   = (short*)(dynsmem + OFF_LABS);
    unsigned short* list   = (unsigned short*)(dynsmem + OFF_LIST);
    int*            ccount = (int*)(dynsmem + OFF_CCOUNT);
    int*            cbase  = (int*)(dynsmem + OFF_CBASE);

    const int tid  = threadIdx.x;
    const int wid  = tid >> 5;            // warp owns classes [8w, 8w+8)
    const int lane = tid & 31;
    const int base_c = wid * CPW;

    const int rows_per = (B + GRID1 - 1) / GRID1;   // 1772
    const int row0  = blockIdx.x * rows_per;
    const int nrows = min(rows_per, B - row0);
    if (nrows <= 0) return;

    for (int i = tid; i < nrows; i += T1) labs[i] = (short)labels[row0 + i];
    __syncthreads();

    // ---- Phase A1: per-class counts ----
    {
        int cnt[CPW];
        #pragma unroll
        for (int k = 0; k < CPW; k++) cnt[k] = 0;
        for (int b = 0; b < nrows; b += 32) {
            int r = b + lane;
            int lab = (r < nrows) ? (int)labs[r] : -1;
            #pragma unroll
            for (int k = 0; k < CPW; k++)
                cnt[k] += __popc(__ballot_sync(FULLM, lab == base_c + k));
        }
        if (lane == 0) {
            #pragma unroll
            for (int k = 0; k < CPW; k++) ccount[base_c + k] = cnt[k];
        }
    }
    __syncthreads();

    // ---- Phase A2: exclusive prefix over 128 class counts (warp 0) ----
    if (wid == 0) {
        int k0 = ccount[lane * 4], k1 = ccount[lane * 4 + 1];
        int k2 = ccount[lane * 4 + 2], k3 = ccount[lane * 4 + 3];
        int s = k0 + k1 + k2 + k3;
        int x = s;
        #pragma unroll
        for (int o = 1; o < 32; o <<= 1) {
            int y = __shfl_up_sync(FULLM, x, o);
            if (lane >= o) x += y;
        }
        int excl = x - s;
        cbase[lane * 4]     = excl;
        cbase[lane * 4 + 1] = excl + k0;
        cbase[lane * 4 + 2] = excl + k0 + k1;
        cbase[lane * 4 + 3] = excl + k0 + k1 + k2;
        if (lane == 31) cbase[CC] = excl + s;
    }
    __syncthreads();

    // ---- Phase A3: fill class-sorted row lists ----
    {
        int off[CPW];
        #pragma unroll
        for (int k = 0; k < CPW; k++) off[k] = cbase[base_c + k];
        unsigned below = (1u << lane) - 1u;
        for (int b = 0; b < nrows; b += 32) {
            int r = b + lane;
            int lab = (r < nrows) ? (int)labs[r] : -1;
            #pragma unroll
            for (int k = 0; k < CPW; k++) {
                unsigned m = __ballot_sync(FULLM, lab == base_c + k);
                if (lab == base_c + k)
                    list[off[k] + __popc(m & below)] = (unsigned short)r;
                off[k] += __popc(m);
            }
        }
    }
    __syncthreads();

    // ---- per-(cta,class) counts + zero partials of empty classes ----
    float* part_cta = g_part + blockIdx.x * (CC * DD);
    const float4 z = make_float4(0.f, 0.f, 0.f, 0.f);
    if (lane < CPW) {
        int c = base_c + lane;
        g_pcnt[blockIdx.x * CC + c] = (float)(cbase[c + 1] - cbase[c]);
    }
    #pragma unroll
    for (int k = 0; k < CPW; k++) {
        int c = base_c + k;
        if (cbase[c + 1] == cbase[c]) {
            float* pp = part_cta + c * DD + (lane << 2);
            *(float4*)pp = z;
            *(float4*)(pp + 128) = z;
        }
    }

    // ---- Phase B: cp.async-staged stream over the warp's sorted range ----
    const int s0 = cbase[base_c], e0 = cbase[base_c + CPW];
    if (s0 < e0) {
        const char* dbytes = (const char*)dirs + (long long)row0 * 1024;
        char* stage_w = dynsmem + OFF_STAGE + wid * (DEPTH * 1024);
        const uint32_t stage_base =
            (uint32_t)__cvta_generic_to_shared(stage_w) + (uint32_t)(lane * 16);

        int cls = base_c;
        while (s0 >= cbase[cls + 1]) cls++;

        // prologue: stage rows s0..s0+PEND-1 into slots 0..PEND-1
        #pragma unroll
        for (int k = 0; k < PEND; k++) {
            if (s0 + k < e0) {
                const char* src = dbytes + (long long)list[s0 + k] * 1024 + lane * 16;
                uint32_t dst = stage_base + k * 1024;
                cp16(dst, src);
                cp16(dst + 512, src + 512);
            }
            asm volatile("cp.async.commit_group;\n" ::: "memory");
        }

        float4 AL = z, AH = z;
        int slot = 0;           // slot holding row i
        int wslot = PEND;       // slot for row i+PEND

        for (int i = s0; i < e0; i++) {
            asm volatile("cp.async.wait_group %0;\n" :: "n"(PEND - 1) : "memory");

            const float4* sp = (const float4*)(stage_w + slot * 1024) + lane;
            float4 a0 = sp[0];
            float4 a1 = sp[32];

            // prefetch row i+PEND into wslot (overwrites a slot consumed
            // 2 iterations ago -> no smem read/write hazard)
            if (i + PEND < e0) {
                const char* src = dbytes + (long long)list[i + PEND] * 1024 + lane * 16;
                uint32_t dst = stage_base + wslot * 1024;
                cp16(dst, src);
                cp16(dst + 512, src + 512);
            }
            asm volatile("cp.async.commit_group;\n" ::: "memory");

            float ss = DOT8(a0, a1);
            #pragma unroll
            for (int o = 16; o > 0; o >>= 1) ss += __shfl_xor_sync(FULLM, ss, o);
            float inv = 1.0f / fmaxf(sqrtf(ss), 1e-12f);
            AXPY4(AL, a0, inv);
            AXPY4(AH, a1, inv);

            if (i + 1 >= cbase[cls + 1]) {   // last row of class cls
                float* pp = part_cta + cls * DD + (lane << 2);
                *(float4*)pp = AL;
                *(float4*)(pp + 128) = AH;
                AL = z; AH = z;
                if (i + 1 < e0) {
                    cls++;
                    while (i + 1 >= cbase[cls + 1]) cls++;
                }
            }

            slot  = (slot + 1)  & (DEPTH - 1);
            wslot = (wslot + 1) & (DEPTH - 1);
        }
    }
}

__device__ __forceinline__ float block_sum256(float v, volatile float* red, int t)
{
    #pragma unroll
    for (int o = 16; o > 0; o >>= 1) v += __shfl_xor_sync(FULLM, v, o);
    __syncthreads();                 // protect red from previous use
    if ((t & 31) == 0) red[t >> 5] = v;
    __syncthreads();
    return red[0] + red[1] + red[2] + red[3] + red[4] + red[5] + red[6] + red[7];
}

__global__ __launch_bounds__(256, 4) void class_kernel(
    const float* __restrict__ v_class,
    const int* __restrict__ step_ptr,
    float* __restrict__ out,
    float Bf)
{
    __shared__ float red[8];
    const int c = blockIdx.x;
    const int t = threadIdx.x;       // dim index, 0..255

    // ---- reduce 148 partials (coalesced, unroll-4 for MLP) ----
    const float* pb = g_part + c * DD + t;
    float sA = 0.f, sB = 0.f, sC = 0.f, sD = 0.f;
    int j = 0;
    for (; j + 4 <= GRID1; j += 4) {
        sA += pb[(j + 0) * (CC * DD)];
        sB += pb[(j + 1) * (CC * DD)];
        sC += pb[(j + 2) * (CC * DD)];
        sD += pb[(j + 3) * (CC * DD)];
    }
    for (; j < GRID1; j++) sA += pb[j * (CC * DD)];
    float s = (sA + sB) + (sC + sD);          // sums_c[t]

    float cv = (t < GRID1) ? g_pcnt[t * CC + c] : 0.f;
    float cnt = block_sum256(cv, red, t);

    float stepf = (float)(*step_ptr);
    float alpha = fminf(0.02f, stepf / (stepf + 50.0f));
    float oma = 1.0f - alpha;

    float invc = 1.0f / fmaxf(cnt, 1.0f);
    float bm = s * invc;

    float nb = block_sum256(bm * bm, red, t);
    float invb = 1.0f / fmaxf(sqrtf(nb), 1e-12f);

    float vc = v_class[c * DD + t];
    float u = oma * vc + alpha * bm * invb;

    float nu = block_sum256(u * u, red, t);
    float invu = 1.0f / fmaxf(sqrtf(nu), 1e-12f);

    float w = (cnt > 0.0f) ? u * invu : vc;
    out[1 + c * DD + t] = w;

    float dot = block_sum256(s * w, red, t);
    if (t == 0) g_dots[c] = dot;
}

__global__ void loss_kernel(float* __restrict__ out, float Bf)
{
    __shared__ float red[4];
    const int t = threadIdx.x;       // 0..127
    float v = g_dots[t];
    #pragma unroll
    for (int o = 16; o > 0; o >>= 1) v += __shfl_xor_sync(FULLM, v, o);
    if ((t & 31) == 0) red[t >> 5] = v;
    __syncthreads();
    if (t == 0)
        out[0] = 0.1f * (1.0f - (red[0] + red[1] + red[2] + red[3]) / Bf);
}

extern "C" void kernel_launch(void* const* d_in, const int* in_sizes, int n_in,
                              void* d_out, int out_size)
{
    const float* dirs    = (const float*)d_in[0];
    const float* v_class = (const float*)d_in[1];
    const int*   labels  = (const int*)d_in[2];
    const int*   step    = (const int*)d_in[3];
    int B = in_sizes[2];

    cudaFuncSetAttribute(accum_kernel,
                         cudaFuncAttributeMaxDynamicSharedMemorySize, SMEM_BYTES);

    accum_kernel<<<GRID1, T1, SMEM_BYTES>>>(dirs, labels, B);
    class_kernel<<<CC, 256>>>(v_class, step, (float*)d_out, (float)B);
    loss_kernel<<<1, 128>>>((float*)d_out, (float)B);
}

// round 9
// speedup vs baseline: 1.0994x; 1.0292x over previous
#include <cuda_runtime.h>
#include <cstdint>

// PrototypeField: B=262144, D=256, C=128.
// out[0] = 0.1*(1 - mean cos_sim), out[1..32768] = new_v (C,D).
//
// Identity: sum_i <dirs_n_i, new_v[label_i]> = sum_c <sums_c, new_v_c>,
// so dirs is read exactly once (268 MB, HBM floor ~34us).
//
// accum_kernel (148 CTAs x 1024 thr = 32 warps/SM, 4 classes/warp):
//   phase A: ballot counting-sort of the CTA's label slice into per-class
//   row lists (smem).
//   phase B: each warp streams its class-sorted rows through a private
//   6-slot x 1KB smem ring via cp.async, TWO rows per iteration with
//   interleaved reduction chains (halves per-row serial cost), 3 groups
//   (6 rows) in flight -> 32 warps x 6KB = 192KB potential in flight/SM.
//   Register accumulators flushed to per-CTA partials with plain STG.128
//   at class boundaries. No atomics, no persistent state to zero.
// class_kernel (128x256): per class, reduce 148 partials + EMA + renorm +
// write new_v + dot.  loss_kernel: sum per-class dots -> out[0].

#define DD 256
#define CC 128
#define GRID1 148
#define T1 1024
#define NW (T1 / 32)          // 32 warps
#define CPW (CC / NW)         // 4 classes per warp
#define FULLM 0xFFFFFFFFu
#define MAXROWS 1792
#define DEPTH 6               // ring slots per warp (3 groups x 2 rows)

// dynamic smem layout (bytes):
//   [0, 196608)           stage: 32 warps x 6 slots x 1024B
//   [196608, 200192)      labs   short[1792]
//   [200192, 203776)      list   ushort[1792]
//   [203776, 204288)      ccount int[128]
//   [204288, 204804)      cbase  int[129]
#define OFF_STAGE  0
#define OFF_LABS   196608
#define OFF_LIST   200192
#define OFF_CCOUNT 203776
#define OFF_CBASE  204288
#define SMEM_BYTES 204816

__device__ float g_part[GRID1 * CC * DD];   // fully overwritten each run
__device__ float g_pcnt[GRID1 * CC];        // fully overwritten each run
__device__ float g_dots[CC];                // fully overwritten each run

#define DOT8(p, q) ((p).x*(p).x + (p).y*(p).y + (p).z*(p).z + (p).w*(p).w \
                  + (q).x*(q).x + (q).y*(q).y + (q).z*(q).z + (q).w*(q).w)
#define AXPY4(acc, v, s) do { (acc).x += (v).x*(s); (acc).y += (v).y*(s); \
                              (acc).z += (v).z*(s); (acc).w += (v).w*(s); } while (0)

__device__ __forceinline__ void cp16(uint32_t dst, const void* src) {
    asm volatile("cp.async.cg.shared.global [%0], [%1], 16;\n"
                 :: "r"(dst), "l"(src) : "memory");
}

__global__ __launch_bounds__(T1, 1) void accum_kernel(
    const float* __restrict__ dirs,
    const int* __restrict__ labels,
    int B)
{
    extern __shared__ char dynsmem[];
    short*          labs   = (short*)(dynsmem + OFF_LABS);
    unsigned short* list   = (unsigned short*)(dynsmem + OFF_LIST);
    int*            ccount = (int*)(dynsmem + OFF_CCOUNT);
    int*            cbase  = (int*)(dynsmem + OFF_CBASE);

    const int tid  = threadIdx.x;
    const int wid  = tid >> 5;            // warp owns classes [4w, 4w+4)
    const int lane = tid & 31;
    const int base_c = wid * CPW;

    const int rows_per = (B + GRID1 - 1) / GRID1;   // 1772
    const int row0  = blockIdx.x * rows_per;
    const int nrows = min(rows_per, B - row0);
    if (nrows <= 0) return;

    for (int i = tid; i < nrows; i += T1) labs[i] = (short)labels[row0 + i];
    __syncthreads();

    // ---- Phase A1: per-class counts ----
    {
        int cnt[CPW];
        #pragma unroll
        for (int k = 0; k < CPW; k++) cnt[k] = 0;
        for (int b = 0; b < nrows; b += 32) {
            int r = b + lane;
            int lab = (r < nrows) ? (int)labs[r] : -1;
            #pragma unroll
            for (int k = 0; k < CPW; k++)
                cnt[k] += __popc(__ballot_sync(FULLM, lab == base_c + k));
        }
        if (lane == 0) {
            #pragma unroll
            for (int k = 0; k < CPW; k++) ccount[base_c + k] = cnt[k];
        }
    }
    __syncthreads();

    // ---- Phase A2: exclusive prefix over 128 class counts (warp 0) ----
    if (wid == 0) {
        int k0 = ccount[lane * 4], k1 = ccount[lane * 4 + 1];
        int k2 = ccount[lane * 4 + 2], k3 = ccount[lane * 4 + 3];
        int s = k0 + k1 + k2 + k3;
        int x = s;
        #pragma unroll
        for (int o = 1; o < 32; o <<= 1) {
            int y = __shfl_up_sync(FULLM, x, o);
            if (lane >= o) x += y;
        }
        int excl = x - s;
        cbase[lane * 4]     = excl;
        cbase[lane * 4 + 1] = excl + k0;
        cbase[lane * 4 + 2] = excl + k0 + k1;
        cbase[lane * 4 + 3] = excl + k0 + k1 + k2;
        if (lane == 31) cbase[CC] = excl + s;
    }
    __syncthreads();

    // ---- Phase A3: fill class-sorted row lists ----
    {
        int off[CPW];
        #pragma unroll
        for (int k = 0; k < CPW; k++) off[k] = cbase[base_c + k];
        unsigned below = (1u << lane) - 1u;
        for (int b = 0; b < nrows; b += 32) {
            int r = b + lane;
            int lab = (r < nrows) ? (int)labs[r] : -1;
            #pragma unroll
            for (int k = 0; k < CPW; k++) {
                unsigned m = __ballot_sync(FULLM, lab == base_c + k);
                if (lab == base_c + k)
                    list[off[k] + __popc(m & below)] = (unsigned short)r;
                off[k] += __popc(m);
            }
        }
    }
    __syncthreads();

    // ---- per-(cta,class) counts + zero partials of empty classes ----
    float* part_cta = g_part + blockIdx.x * (CC * DD);
    const float4 z = make_float4(0.f, 0.f, 0.f, 0.f);
    if (lane < CPW) {
        int c = base_c + lane;
        g_pcnt[blockIdx.x * CC + c] = (float)(cbase[c + 1] - cbase[c]);
    }
    #pragma unroll
    for (int k = 0; k < CPW; k++) {
        int c = base_c + k;
        if (cbase[c + 1] == cbase[c]) {
            float* pp = part_cta + c * DD + (lane << 2);
            *(float4*)pp = z;
            *(float4*)(pp + 128) = z;
        }
    }

    // ---- Phase B: cp.async ring, 2 rows/iter, interleaved chains ----
    const int s0 = cbase[base_c], e0 = cbase[base_c + CPW];
    if (s0 < e0) {
        const char* dbytes = (const char*)dirs + (long long)row0 * 1024;
        char* stage_w = dynsmem + OFF_STAGE + wid * (DEPTH * 1024);
        const uint32_t stage_base =
            (uint32_t)__cvta_generic_to_shared(stage_w) + (uint32_t)(lane * 16);

        int cls = base_c;
        while (s0 >= cbase[cls + 1]) cls++;
        int cend = cbase[cls + 1];

        // prologue: 3 groups of up-to-2 rows into slots 0..5
        #pragma unroll
        for (int g = 0; g < 3; g++) {
            int r0 = s0 + 2 * g, r1 = r0 + 1;
            if (r0 < e0) {
                const char* src = dbytes + (long long)list[r0] * 1024 + lane * 16;
                uint32_t dst = stage_base + (2 * g) * 1024;
                cp16(dst, src); cp16(dst + 512, src + 512);
            }
            if (r1 < e0) {
                const char* src = dbytes + (long long)list[r1] * 1024 + lane * 16;
                uint32_t dst = stage_base + (2 * g + 1) * 1024;
                cp16(dst, src); cp16(dst + 512, src + 512);
            }
            asm volatile("cp.async.commit_group;\n" ::: "memory");
        }

        float4 AL = z, AH = z;
        int slotA = 0;                       // cycles 0,2,4

        for (int i = s0; i < e0; i += 2) {
            asm volatile("cp.async.wait_group 2;\n" ::: "memory");

            const float4* spA = (const float4*)(stage_w + slotA * 1024) + lane;
            const float4* spB = (const float4*)(stage_w + (slotA + 1) * 1024) + lane;
            float4 a0 = spA[0], a1 = spA[32];
            float4 b0 = spB[0], b1 = spB[32];   // garbage if i+1>=e0 (unused)
            const bool two = (i + 1 < e0);

            // prefetch rows i+6, i+7 into the slots just consumed
            if (i + 6 < e0) {
                const char* src = dbytes + (long long)list[i + 6] * 1024 + lane * 16;
                uint32_t dst = stage_base + slotA * 1024;
                cp16(dst, src); cp16(dst + 512, src + 512);
            }
            if (i + 7 < e0) {
                const char* src = dbytes + (long long)list[i + 7] * 1024 + lane * 16;
                uint32_t dst = stage_base + (slotA + 1) * 1024;
                cp16(dst, src); cp16(dst + 512, src + 512);
            }
            asm volatile("cp.async.commit_group;\n" ::: "memory");

            // interleaved dual reduction
            float sa = DOT8(a0, a1);
            float sb = DOT8(b0, b1);
            #pragma unroll
            for (int o = 16; o > 0; o >>= 1) {
                sa += __shfl_xor_sync(FULLM, sa, o);
                sb += __shfl_xor_sync(FULLM, sb, o);
            }
            float inva = 1.0f / fmaxf(sqrtf(sa), 1e-12f);
            AXPY4(AL, a0, inva);
            AXPY4(AH, a1, inva);

            if (i + 1 >= cend) {             // row i is last of cls
                float* pp = part_cta + cls * DD + (lane << 2);
                *(float4*)pp = AL;
                *(float4*)(pp + 128) = AH;
                AL = z; AH = z;
                if (i + 1 < e0) {
                    cls++;
                    while (i + 1 >= cbase[cls + 1]) cls++;
                    cend = cbase[cls + 1];
                }
            }

            if (two) {
                float invb = 1.0f / fmaxf(sqrtf(sb), 1e-12f);
                AXPY4(AL, b0, invb);
                AXPY4(AH, b1, invb);

                if (i + 2 >= cend) {         // row i+1 is last of cls
                    float* pp = part_cta + cls * DD + (lane << 2);
                    *(float4*)pp = AL;
                    *(float4*)(pp + 128) = AH;
                    AL = z; AH = z;
                    if (i + 2 < e0) {
                        cls++;
                        while (i + 2 >= cbase[cls + 1]) cls++;
                        cend = cbase[cls + 1];
                    }
                }
            }

            slotA += 2;
            if (slotA == DEPTH) slotA = 0;
        }
    }
}

__device__ __forceinline__ float block_sum256(float v, volatile float* red, int t)
{
    #pragma unroll
    for (int o = 16; o > 0; o >>= 1) v += __shfl_xor_sync(FULLM, v, o);
    __syncthreads();                 // protect red from previous use
    if ((t & 31) == 0) red[t >> 5] = v;
    __syncthreads();
    return red[0] + red[1] + red[2] + red[3] + red[4] + red[5] + red[6] + red[7];
}

__global__ __launch_bounds__(256, 4) void class_kernel(
    const float* __restrict__ v_class,
    const int* __restrict__ step_ptr,
    float* __restrict__ out,
    float Bf)
{
    __shared__ float red[8];
    const int c = blockIdx.x;
    const int t = threadIdx.x;       // dim index, 0..255

    // ---- reduce 148 partials (coalesced, unroll-4 for MLP) ----
    const float* pb = g_part + c * DD + t;
    float sA = 0.f, sB = 0.f, sC = 0.f, sD = 0.f;
    int j = 0;
    for (; j + 4 <= GRID1; j += 4) {
        sA += pb[(j + 0) * (CC * DD)];
        sB += pb[(j + 1) * (CC * DD)];
        sC += pb[(j + 2) * (CC * DD)];
        sD += pb[(j + 3) * (CC * DD)];
    }
    for (; j < GRID1; j++) sA += pb[j * (CC * DD)];
    float s = (sA + sB) + (sC + sD);          // sums_c[t]

    float cv = (t < GRID1) ? g_pcnt[t * CC + c] : 0.f;
    float cnt = block_sum256(cv, red, t);

    float stepf = (float)(*step_ptr);
    float alpha = fminf(0.02f, stepf / (stepf + 50.0f));
    float oma = 1.0f - alpha;

    float invc = 1.0f / fmaxf(cnt, 1.0f);
    float bm = s * invc;

    float nb = block_sum256(bm * bm, red, t);
    float invb = 1.0f / fmaxf(sqrtf(nb), 1e-12f);

    float vc = v_class[c * DD + t];
    float u = oma * vc + alpha * bm * invb;

    float nu = block_sum256(u * u, red, t);
    float invu = 1.0f / fmaxf(sqrtf(nu), 1e-12f);

    float w = (cnt > 0.0f) ? u * invu : vc;
    out[1 + c * DD + t] = w;

    float dot = block_sum256(s * w, red, t);
    if (t == 0) g_dots[c] = dot;
}

__global__ void loss_kernel(float* __restrict__ out, float Bf)
{
    __shared__ float red[4];
    const int t = threadIdx.x;       // 0..127
    float v = g_dots[t];
    #pragma unroll
    for (int o = 16; o > 0; o >>= 1) v += __shfl_xor_sync(FULLM, v, o);
    if ((t & 31) == 0) red[t >> 5] = v;
    __syncthreads();
    if (t == 0)
        out[0] = 0.1f * (1.0f - (red[0] + red[1] + red[2] + red[3]) / Bf);
}

extern "C" void kernel_launch(void* const* d_in, const int* in_sizes, int n_in,
                              void* d_out, int out_size)
{
    const float* dirs    = (const float*)d_in[0];
    const float* v_class = (const float*)d_in[1];
    const int*   labels  = (const int*)d_in[2];
    const int*   step    = (const int*)d_in[3];
    int B = in_sizes[2];

    cudaFuncSetAttribute(accum_kernel,
                         cudaFuncAttributeMaxDynamicSharedMemorySize, SMEM_BYTES);

    accum_kernel<<<GRID1, T1, SMEM_BYTES>>>(dirs, labels, B);
    class_kernel<<<CC, 256>>>(v_class, step, (float*)d_out, (float)B);
    loss_kernel<<<1, 128>>>((float*)d_out, (float)B);
}

// round 12
// speedup vs baseline: 1.4698x; 1.3369x over previous
#include <cuda_runtime.h>
#include <cstdint>

// PrototypeField: B=262144, D=256, C=128.
// out[0] = 0.1*(1 - mean cos_sim), out[1..32768] = new_v (C,D).
//
// Identity: sum_i <dirs_n_i, new_v[label_i]> = sum_c <sums_c, new_v_c>,
// so dirs is read exactly once (268 MB, HBM floor ~34us).
//
// accum_kernel (148 CTAs x 1024 thr, 4 classes/warp):
//   phase A (cheap, match.any-based): each warp counts+scatters ONLY its
//   own 56-row chunk; cross-warp per-class exclusive scan gives each warp
//   its deterministic base offset per class. ~3k issue slots/SM vs ~43k
//   for the old all-rows ballot sort.
//   phase B: per-warp 6-slot x 1KB cp.async ring, 2 rows/iter, dual
//   interleaved 5-shfl allreduces + MUFU.RSQ; register accumulators
//   flushed with STG.128 at class boundaries per CTA (no atomics).
// class_kernel (128x256): per class, reduce 148 partials + EMA + renorm +
// write new_v + dot; last CTA computes the loss (fused, counter resets).

#define DD 256
#define CC 128
#define GRID1 148
#define T1 1024
#define NW (T1 / 32)          // 32 warps
#define CPW (CC / NW)         // 4 classes per warp
#define FULLM 0xFFFFFFFFu
#define DEPTH 6               // ring slots per warp (3 groups x 2 rows)
#define WSTRIDE 129           // padded woff row stride (bank-conflict-free)

// dynamic smem layout (bytes):
//   [0, 196608)           stage: 32 warps x 6 slots x 1024B
//   [196608, 213120)      woff   int[32*129] (counts -> offsets -> cursors)
//   [213120, 216704)      list   ushort[1792]
//   [216704, 217216)      ccount int[128]
//   [217216, 217732)      cbase  int[129]
#define OFF_STAGE  0
#define OFF_WOFF   196608
#define OFF_LIST   213120
#define OFF_CCOUNT 216704
#define OFF_CBASE  217216
#define SMEM_BYTES 217760

__device__ float g_part[GRID1 * CC * DD];     // fully overwritten each run
__device__ float g_pcnt[GRID1 * CC];          // fully overwritten each run
__device__ float g_dots[CC];                  // fully overwritten each run
__device__ unsigned int g_done;               // 0; self-resetting counter

#define DOT8(p, q) ((p).x*(p).x + (p).y*(p).y + (p).z*(p).z + (p).w*(p).w \
                  + (q).x*(q).x + (q).y*(q).y + (q).z*(q).z + (q).w*(q).w)
#define AXPY4(acc, v, s) do { (acc).x += (v).x*(s); (acc).y += (v).y*(s); \
                              (acc).z += (v).z*(s); (acc).w += (v).w*(s); } while (0)

__device__ __forceinline__ void cp16(uint32_t dst, const void* src) {
    asm volatile("cp.async.cg.shared.global [%0], [%1], 16;\n"
                 :: "r"(dst), "l"(src) : "memory");
}

__device__ __forceinline__ float warp_sum(float v) {
    #pragma unroll
    for (int o = 16; o > 0; o >>= 1) v += __shfl_xor_sync(FULLM, v, o);
    return v;
}

__global__ __launch_bounds__(T1, 1) void accum_kernel(
    const float* __restrict__ dirs,
    const int* __restrict__ labels,
    int B)
{
    extern __shared__ char dynsmem[];
    int*            woff   = (int*)(dynsmem + OFF_WOFF);
    unsigned short* list   = (unsigned short*)(dynsmem + OFF_LIST);
    int*            ccount = (int*)(dynsmem + OFF_CCOUNT);
    int*            cbase  = (int*)(dynsmem + OFF_CBASE);

    const int tid  = threadIdx.x;
    const int wid  = tid >> 5;            // warp owns classes [4w, 4w+4)
    const int lane = tid & 31;
    const int base_c = wid * CPW;

    const int rows_per = (B + GRID1 - 1) / GRID1;   // 1772
    const int row0  = blockIdx.x * rows_per;
    const int nrows = min(rows_per, B - row0);
    if (nrows <= 0) return;

    // warp's contiguous row chunk (rpw <= 56, so exactly 2 sub-chunks of 32)
    const int rpw    = (nrows + NW - 1) / NW;
    const int wstart = wid * rpw;
    const int wend   = min(wstart + rpw, nrows);

    // ---- Phase A1: per-warp per-class counts via match.any ----
    for (int c = lane; c < CC; c += 32) woff[wid * WSTRIDE + c] = 0;
    __syncwarp();
    int labreg[2];
    #pragma unroll
    for (int ch = 0; ch < 2; ch++) {
        int r = wstart + ch * 32 + lane;
        int lab = (r < wend) ? labels[row0 + r] : -1;
        labreg[ch] = lab;
        unsigned m = __match_any_sync(FULLM, lab);
        unsigned below = (1u << lane) - 1u;
        if (lab >= 0 && __popc(m & below) == 0)      // leader of its group
            woff[wid * WSTRIDE + lab] += __popc(m);
        __syncwarp();
    }
    __syncthreads();

    // ---- Phase A2a: cross-warp exclusive scan per class ----
    // warp W scans classes {4W..4W+3}; lane indexes the warp dimension.
    #pragma unroll
    for (int k = 0; k < CPW; k++) {
        int c = base_c + k;
        int v = woff[lane * WSTRIDE + c];
        int x = v;
        #pragma unroll
        for (int o = 1; o < 32; o <<= 1) {
            int y = __shfl_up_sync(FULLM, x, o);
            if (lane >= o) x += y;
        }
        woff[lane * WSTRIDE + c] = x - v;            // exclusive within class
        if (lane == 31) ccount[c] = x;               // class total
    }
    __syncthreads();

    // ---- Phase A2b: exclusive prefix over class totals (warp 0) ----
    if (wid == 0) {
        int k0 = ccount[lane * 4], k1 = ccount[lane * 4 + 1];
        int k2 = ccount[lane * 4 + 2], k3 = ccount[lane * 4 + 3];
        int s = k0 + k1 + k2 + k3;
        int x = s;
        #pragma unroll
        for (int o = 1; o < 32; o <<= 1) {
            int y = __shfl_up_sync(FULLM, x, o);
            if (lane >= o) x += y;
        }
        int excl = x - s;
        cbase[lane * 4]     = excl;
        cbase[lane * 4 + 1] = excl + k0;
        cbase[lane * 4 + 2] = excl + k0 + k1;
        cbase[lane * 4 + 3] = excl + k0 + k1 + k2;
        if (lane == 31) cbase[CC] = excl + s;
    }
    __syncthreads();

    // woff[w][c] += cbase[c]  -> absolute write cursor per (warp, class)
    for (int i = tid; i < NW * CC; i += T1) {
        int w = i >> 7, c = i & (CC - 1);
        woff[w * WSTRIDE + c] += cbase[c];
    }
    __syncthreads();

    // ---- Phase A3: scatter own rows via match.any (deterministic) ----
    #pragma unroll
    for (int ch = 0; ch < 2; ch++) {
        int r = wstart + ch * 32 + lane;
        int lab = labreg[ch];
        unsigned m = __match_any_sync(FULLM, lab);
        unsigned below = (1u << lane) - 1u;
        int rank = __popc(m & below);
        int base = (lab >= 0) ? woff[wid * WSTRIDE + lab] : 0;
        __syncwarp();
        if (lab >= 0) {
            if (rank == 0) woff[wid * WSTRIDE + lab] = base + __popc(m);
            list[base + rank] = (unsigned short)r;
        }
        __syncwarp();
    }
    __syncthreads();

    // ---- per-(cta,class) counts + zero partials of empty classes ----
    float* part_cta = g_part + blockIdx.x * (CC * DD);
    const float4 z = make_float4(0.f, 0.f, 0.f, 0.f);
    if (tid < CC) g_pcnt[blockIdx.x * CC + tid] = (float)ccount[tid];
    #pragma unroll
    for (int k = 0; k < CPW; k++) {
        int c = base_c + k;
        if (cbase[c + 1] == cbase[c]) {
            float* pp = part_cta + c * DD + (lane << 2);
            *(float4*)pp = z;
            *(float4*)(pp + 128) = z;
        }
    }

    // ---- Phase B: cp.async ring, 2 rows/iter, dual shfl allreduce ----
    const int s0 = cbase[base_c], e0 = cbase[base_c + CPW];
    if (s0 < e0) {
        const char* dbytes = (const char*)dirs + (long long)row0 * 1024;
        char* stage_w = dynsmem + OFF_STAGE + wid * (DEPTH * 1024);
        const uint32_t stage_base =
            (uint32_t)__cvta_generic_to_shared(stage_w) + (uint32_t)(lane * 16);

        int cls = base_c;
        while (s0 >= cbase[cls + 1]) cls++;
        int cend = cbase[cls + 1];

        // prologue: 3 groups of up-to-2 rows into slots 0..5
        #pragma unroll
        for (int g = 0; g < 3; g++) {
            int r0 = s0 + 2 * g, r1 = r0 + 1;
            if (r0 < e0) {
                const char* src = dbytes + (long long)list[r0] * 1024 + lane * 16;
                uint32_t dst = stage_base + (2 * g) * 1024;
                cp16(dst, src); cp16(dst + 512, src + 512);
            }
            if (r1 < e0) {
                const char* src = dbytes + (long long)list[r1] * 1024 + lane * 16;
                uint32_t dst = stage_base + (2 * g + 1) * 1024;
                cp16(dst, src); cp16(dst + 512, src + 512);
            }
            asm volatile("cp.async.commit_group;\n" ::: "memory");
        }

        float4 AL = z, AH = z;
        int slotA = 0;                       // cycles 0,2,4

        for (int i = s0; i < e0; i += 2) {
            asm volatile("cp.async.wait_group 2;\n" ::: "memory");

            const float4* spA = (const float4*)(stage_w + slotA * 1024) + lane;
            const float4* spB = (const float4*)(stage_w + (slotA + 1) * 1024) + lane;
            float4 a0 = spA[0], a1 = spA[32];
            float4 b0 = spB[0], b1 = spB[32];   // garbage if i+1>=e0 (unused)
            const bool two = (i + 1 < e0);

            // prefetch rows i+6, i+7 into the slots just consumed
            if (i + 6 < e0) {
                const char* src = dbytes + (long long)list[i + 6] * 1024 + lane * 16;
                uint32_t dst = stage_base + slotA * 1024;
                cp16(dst, src); cp16(dst + 512, src + 512);
            }
            if (i + 7 < e0) {
                const char* src = dbytes + (long long)list[i + 7] * 1024 + lane * 16;
                uint32_t dst = stage_base + (slotA + 1) * 1024;
                cp16(dst, src); cp16(dst + 512, src + 512);
            }
            asm volatile("cp.async.commit_group;\n" ::: "memory");

            // dual interleaved allreduce (hides shfl latency)
            float sa = DOT8(a0, a1);
            float sb = DOT8(b0, b1);
            #pragma unroll
            for (int o = 16; o > 0; o >>= 1) {
                sa += __shfl_xor_sync(FULLM, sa, o);
                sb += __shfl_xor_sync(FULLM, sb, o);
            }

            // rsqrt(max(s,1e-24)) == 1/max(sqrt(s),1e-12) for all s
            float inva = rsqrtf(fmaxf(sa, 1e-24f));
            AXPY4(AL, a0, inva);
            AXPY4(AH, a1, inva);

            if (i + 1 >= cend) {             // row i is last of cls
                float* pp = part_cta + cls * DD + (lane << 2);
                *(float4*)pp = AL;
                *(float4*)(pp + 128) = AH;
                AL = z; AH = z;
                if (i + 1 < e0) {
                    cls++;
                    while (i + 1 >= cbase[cls + 1]) cls++;
                    cend = cbase[cls + 1];
                }
            }

            if (two) {
                float invb = rsqrtf(fmaxf(sb, 1e-24f));
                AXPY4(AL, b0, invb);
                AXPY4(AH, b1, invb);

                if (i + 2 >= cend) {         // row i+1 is last of cls
                    float* pp = part_cta + cls * DD + (lane << 2);
                    *(float4*)pp = AL;
                    *(float4*)(pp + 128) = AH;
                    AL = z; AH = z;
                    if (i + 2 < e0) {
                        cls++;
                        while (i + 2 >= cbase[cls + 1]) cls++;
                        cend = cbase[cls + 1];
                    }
                }
            }

            slotA += 2;
            if (slotA == DEPTH) slotA = 0;
        }
    }
}

__device__ __forceinline__ float block_sum256(float v, volatile float* red, int t)
{
    v = warp_sum(v);
    __syncthreads();                 // protect red from previous use
    if ((t & 31) == 0) red[t >> 5] = v;
    __syncthreads();
    return red[0] + red[1] + red[2] + red[3] + red[4] + red[5] + red[6] + red[7];
}

__global__ __launch_bounds__(256, 4) void class_kernel(
    const float* __restrict__ v_class,
    const int* __restrict__ step_ptr,
    float* __restrict__ out,
    float Bf)
{
    __shared__ float red[8];
    __shared__ bool amLast;
    const int c = blockIdx.x;
    const int t = threadIdx.x;       // dim index, 0..255

    // ---- reduce 148 partials (coalesced, unroll-4 for MLP) ----
    const float* pb = g_part + c * DD + t;
    float sA = 0.f, sB = 0.f, sC = 0.f, sD = 0.f;
    int j = 0;
    for (; j + 4 <= GRID1; j += 4) {
        sA += pb[(j + 0) * (CC * DD)];
        sB += pb[(j + 1) * (CC * DD)];
        sC += pb[(j + 2) * (CC * DD)];
        sD += pb[(j + 3) * (CC * DD)];
    }
    for (; j < GRID1; j++) sA += pb[j * (CC * DD)];
    float s = (sA + sB) + (sC + sD);          // sums_c[t]

    float cv = (t < GRID1) ? g_pcnt[t * CC + c] : 0.f;
    float cnt = block_sum256(cv, red, t);

    float stepf = (float)(*step_ptr);
    float alpha = fminf(0.02f, stepf / (stepf + 50.0f));
    float oma = 1.0f - alpha;

    float invc = 1.0f / fmaxf(cnt, 1.0f);
    float bm = s * invc;

    float nb = block_sum256(bm * bm, red, t);
    float invb = 1.0f / fmaxf(sqrtf(nb), 1e-12f);

    float vc = v_class[c * DD + t];
    float u = oma * vc + alpha * bm * invb;

    float nu = block_sum256(u * u, red, t);
    float invu = 1.0f / fmaxf(sqrtf(nu), 1e-12f);

    float w = (cnt > 0.0f) ? u * invu : vc;
    out[1 + c * DD + t] = w;

    float dot = block_sum256(s * w, red, t);
    if (t == 0) g_dots[c] = dot;

    // ---- fused loss: last CTA to finish sums g_dots ----
    if (t == 0) {
        __threadfence();
        amLast = (atomicAdd(&g_done, 1u) == CC - 1);
    }
    __syncthreads();
    if (amLast) {
        float v = (t < CC) ? g_dots[t] : 0.f;
        float tot = block_sum256(v, red, t);
        if (t == 0) {
            out[0] = 0.1f * (1.0f - tot / Bf);
            g_done = 0;              // reset for next graph replay
        }
    }
}

extern "C" void kernel_launch(void* const* d_in, const int* in_sizes, int n_in,
                              void* d_out, int out_size)
{
    const float* dirs    = (const float*)d_in[0];
    const float* v_class = (const float*)d_in[1];
    const int*   labels  = (const int*)d_in[2];
    const int*   step    = (const int*)d_in[3];
    int B = in_sizes[2];

    cudaFuncSetAttribute(accum_kernel,
                         cudaFuncAttributeMaxDynamicSharedMemorySize, SMEM_BYTES);

    accum_kernel<<<GRID1, T1, SMEM_BYTES>>>(dirs, labels, B);
    class_kernel<<<CC, 256>>>(v_class, step, (float*)d_out, (float)B);
}

// round 14
// speedup vs baseline: 1.6023x; 1.0902x over previous
#include <cuda_runtime.h>
#include <cstdint>

// PrototypeField: B=262144, D=256, C=128.
// out[0] = 0.1*(1 - mean cos_sim), out[1..32768] = new_v (C,D).
//
// Identity: sum_i <dirs_n_i, new_v[label_i]> = sum_c <sums_c, new_v_c>,
// so dirs is read exactly once (268 MB, HBM floor ~34us).
//
// accum_kernel (148 CTAs x 1024 thr, 4 classes/warp):
//   phase A (match.any): each warp counts+scatters ONLY its own 56-row
//   chunk; cross-warp per-class exclusive scan gives deterministic offsets.
//   phase B: per-warp 6-slot x 1KB cp.async ring, 2 rows/iter, dual
//   interleaved 5-shfl allreduces + MUFU.RSQ; register accumulators
//   flushed with red.global.v4.f32 (atomicAdd float4) into g_sums at
//   class boundaries -- no partials array, no extra 19MB of traffic.
// class_kernel (128x256): per class, read g_sums/g_counts + EMA + renorm +
// write new_v + dot, then RE-ZERO its class slice (replay-invariant);
// last CTA computes the loss (fused, counter resets).

#define DD 256
#define CC 128
#define GRID1 148
#define T1 1024
#define NW (T1 / 32)          // 32 warps
#define CPW (CC / NW)         // 4 classes per warp
#define FULLM 0xFFFFFFFFu
#define DEPTH 6               // ring slots per warp (3 groups x 2 rows)
#define WSTRIDE 129           // padded woff row stride (bank-conflict-free)

// dynamic smem layout (bytes):
//   [0, 196608)           stage: 32 warps x 6 slots x 1024B
//   [196608, 213120)      woff   int[32*129] (counts -> offsets -> cursors)
//   [213120, 216704)      list   ushort[1792]
//   [216704, 217216)      ccount int[128]
//   [217216, 217732)      cbase  int[129]
#define OFF_STAGE  0
#define OFF_WOFF   196608
#define OFF_LIST   213120
#define OFF_CCOUNT 216704
#define OFF_CBASE  217216
#define SMEM_BYTES 217760

__device__ float g_sums[CC * DD];             // zero at load; re-zeroed by class_kernel
__device__ float g_counts[CC];                // zero at load; re-zeroed by class_kernel
__device__ float g_dots[CC];                  // fully overwritten each run
__device__ unsigned int g_done;               // 0; self-resetting counter

#define DOT8(p, q) ((p).x*(p).x + (p).y*(p).y + (p).z*(p).z + (p).w*(p).w \
                  + (q).x*(q).x + (q).y*(q).y + (q).z*(q).z + (q).w*(q).w)
#define AXPY4(acc, v, s) do { (acc).x += (v).x*(s); (acc).y += (v).y*(s); \
                              (acc).z += (v).z*(s); (acc).w += (v).w*(s); } while (0)

__device__ __forceinline__ void cp16(uint32_t dst, const void* src) {
    asm volatile("cp.async.cg.shared.global [%0], [%1], 16;\n"
                 :: "r"(dst), "l"(src) : "memory");
}

__device__ __forceinline__ float warp_sum(float v) {
    #pragma unroll
    for (int o = 16; o > 0; o >>= 1) v += __shfl_xor_sync(FULLM, v, o);
    return v;
}

__global__ __launch_bounds__(T1, 1) void accum_kernel(
    const float* __restrict__ dirs,
    const int* __restrict__ labels,
    int B)
{
    extern __shared__ char dynsmem[];
    int*            woff   = (int*)(dynsmem + OFF_WOFF);
    unsigned short* list   = (unsigned short*)(dynsmem + OFF_LIST);
    int*            ccount = (int*)(dynsmem + OFF_CCOUNT);
    int*            cbase  = (int*)(dynsmem + OFF_CBASE);

    const int tid  = threadIdx.x;
    const int wid  = tid >> 5;            // warp owns classes [4w, 4w+4)
    const int lane = tid & 31;
    const int base_c = wid * CPW;

    const int rows_per = (B + GRID1 - 1) / GRID1;   // 1772
    const int row0  = blockIdx.x * rows_per;
    const int nrows = min(rows_per, B - row0);
    if (nrows <= 0) return;

    // warp's contiguous row chunk (rpw <= 56, so exactly 2 sub-chunks of 32)
    const int rpw    = (nrows + NW - 1) / NW;
    const int wstart = wid * rpw;
    const int wend   = min(wstart + rpw, nrows);

    // ---- Phase A1: per-warp per-class counts via match.any ----
    for (int c = lane; c < CC; c += 32) woff[wid * WSTRIDE + c] = 0;
    __syncwarp();
    int labreg[2];
    #pragma unroll
    for (int ch = 0; ch < 2; ch++) {
        int r = wstart + ch * 32 + lane;
        int lab = (r < wend) ? labels[row0 + r] : -1;
        labreg[ch] = lab;
        unsigned m = __match_any_sync(FULLM, lab);
        unsigned below = (1u << lane) - 1u;
        if (lab >= 0 && __popc(m & below) == 0)      // leader of its group
            woff[wid * WSTRIDE + lab] += __popc(m);
        __syncwarp();
    }
    __syncthreads();

    // ---- Phase A2a: cross-warp exclusive scan per class ----
    #pragma unroll
    for (int k = 0; k < CPW; k++) {
        int c = base_c + k;
        int v = woff[lane * WSTRIDE + c];
        int x = v;
        #pragma unroll
        for (int o = 1; o < 32; o <<= 1) {
            int y = __shfl_up_sync(FULLM, x, o);
            if (lane >= o) x += y;
        }
        woff[lane * WSTRIDE + c] = x - v;            // exclusive within class
        if (lane == 31) ccount[c] = x;               // class total
    }
    __syncthreads();

    // ---- Phase A2b: exclusive prefix over class totals (warp 0) ----
    if (wid == 0) {
        int k0 = ccount[lane * 4], k1 = ccount[lane * 4 + 1];
        int k2 = ccount[lane * 4 + 2], k3 = ccount[lane * 4 + 3];
        int s = k0 + k1 + k2 + k3;
        int x = s;
        #pragma unroll
        for (int o = 1; o < 32; o <<= 1) {
            int y = __shfl_up_sync(FULLM, x, o);
            if (lane >= o) x += y;
        }
        int excl = x - s;
        cbase[lane * 4]     = excl;
        cbase[lane * 4 + 1] = excl + k0;
        cbase[lane * 4 + 2] = excl + k0 + k1;
        cbase[lane * 4 + 3] = excl + k0 + k1 + k2;
        if (lane == 31) cbase[CC] = excl + s;
    }
    __syncthreads();

    // woff[w][c] += cbase[c]  -> absolute write cursor per (warp, class)
    for (int i = tid; i < NW * CC; i += T1) {
        int w = i >> 7, c = i & (CC - 1);
        woff[w * WSTRIDE + c] += cbase[c];
    }
    __syncthreads();

    // ---- Phase A3: scatter own rows via match.any (deterministic) ----
    #pragma unroll
    for (int ch = 0; ch < 2; ch++) {
        int r = wstart + ch * 32 + lane;
        int lab = labreg[ch];
        unsigned m = __match_any_sync(FULLM, lab);
        unsigned below = (1u << lane) - 1u;
        int rank = __popc(m & below);
        int base = (lab >= 0) ? woff[wid * WSTRIDE + lab] : 0;
        __syncwarp();
        if (lab >= 0) {
            if (rank == 0) woff[wid * WSTRIDE + lab] = base + __popc(m);
            list[base + rank] = (unsigned short)r;
        }
        __syncwarp();
    }
    __syncthreads();

    // ---- flush per-CTA class counts (REDG, fire-and-forget) ----
    if (tid < CC && ccount[tid] > 0)
        atomicAdd(&g_counts[tid], (float)ccount[tid]);

    // ---- Phase B: cp.async ring, 2 rows/iter, dual shfl allreduce ----
    const int s0 = cbase[base_c], e0 = cbase[base_c + CPW];
    if (s0 < e0) {
        const char* dbytes = (const char*)dirs + (long long)row0 * 1024;
        char* stage_w = dynsmem + OFF_STAGE + wid * (DEPTH * 1024);
        const uint32_t stage_base =
            (uint32_t)__cvta_generic_to_shared(stage_w) + (uint32_t)(lane * 16);
        const float4 z = make_float4(0.f, 0.f, 0.f, 0.f);

        int cls = base_c;
        while (s0 >= cbase[cls + 1]) cls++;
        int cend = cbase[cls + 1];

        // prologue: 3 groups of up-to-2 rows into slots 0..5
        #pragma unroll
        for (int g = 0; g < 3; g++) {
            int r0 = s0 + 2 * g, r1 = r0 + 1;
            if (r0 < e0) {
                const char* src = dbytes + (long long)list[r0] * 1024 + lane * 16;
                uint32_t dst = stage_base + (2 * g) * 1024;
                cp16(dst, src); cp16(dst + 512, src + 512);
            }
            if (r1 < e0) {
                const char* src = dbytes + (long long)list[r1] * 1024 + lane * 16;
                uint32_t dst = stage_base + (2 * g + 1) * 1024;
                cp16(dst, src); cp16(dst + 512, src + 512);
            }
            asm volatile("cp.async.commit_group;\n" ::: "memory");
        }

        float4 AL = z, AH = z;
        int slotA = 0;                       // cycles 0,2,4

        for (int i = s0; i < e0; i += 2) {
            asm volatile("cp.async.wait_group 2;\n" ::: "memory");

            const float4* spA = (const float4*)(stage_w + slotA * 1024) + lane;
            const float4* spB = (const float4*)(stage_w + (slotA + 1) * 1024) + lane;
            float4 a0 = spA[0], a1 = spA[32];
            float4 b0 = spB[0], b1 = spB[32];   // garbage if i+1>=e0 (unused)
            const bool two = (i + 1 < e0);

            // prefetch rows i+6, i+7 into the slots just consumed
            if (i + 6 < e0) {
                const char* src = dbytes + (long long)list[i + 6] * 1024 + lane * 16;
                uint32_t dst = stage_base + slotA * 1024;
                cp16(dst, src); cp16(dst + 512, src + 512);
            }
            if (i + 7 < e0) {
                const char* src = dbytes + (long long)list[i + 7] * 1024 + lane * 16;
                uint32_t dst = stage_base + (slotA + 1) * 1024;
                cp16(dst, src); cp16(dst + 512, src + 512);
            }
            asm volatile("cp.async.commit_group;\n" ::: "memory");

            // dual interleaved allreduce (hides shfl latency)
            float sa = DOT8(a0, a1);
            float sb = DOT8(b0, b1);
            #pragma unroll
            for (int o = 16; o > 0; o >>= 1) {
                sa += __shfl_xor_sync(FULLM, sa, o);
                sb += __shfl_xor_sync(FULLM, sb, o);
            }

            // rsqrt(max(s,1e-24)) == 1/max(sqrt(s),1e-12) for all s
            float inva = rsqrtf(fmaxf(sa, 1e-24f));
            AXPY4(AL, a0, inva);
            AXPY4(AH, a1, inva);

            if (i + 1 >= cend) {             // row i is last of cls
                float* sp = g_sums + cls * DD + (lane << 2);
                atomicAdd((float4*)sp, AL);
                atomicAdd((float4*)(sp + 128), AH);
                AL = z; AH = z;
                if (i + 1 < e0) {
                    cls++;
                    while (i + 1 >= cbase[cls + 1]) cls++;
                    cend = cbase[cls + 1];
                }
            }

            if (two) {
                float invb = rsqrtf(fmaxf(sb, 1e-24f));
                AXPY4(AL, b0, invb);
                AXPY4(AH, b1, invb);

                if (i + 2 >= cend) {         // row i+1 is last of cls
                    float* sp = g_sums + cls * DD + (lane << 2);
                    atomicAdd((float4*)sp, AL);
                    atomicAdd((float4*)(sp + 128), AH);
                    AL = z; AH = z;
                    if (i + 2 < e0) {
                        cls++;
                        while (i + 2 >= cbase[cls + 1]) cls++;
                        cend = cbase[cls + 1];
                    }
                }
            }

            slotA += 2;
            if (slotA == DEPTH) slotA = 0;
        }
    }
}

__device__ __forceinline__ float block_sum256(float v, volatile float* red, int t)
{
    v = warp_sum(v);
    __syncthreads();                 // protect red from previous use
    if ((t & 31) == 0) red[t >> 5] = v;
    __syncthreads();
    return red[0] + red[1] + red[2] + red[3] + red[4] + red[5] + red[6] + red[7];
}

__global__ __launch_bounds__(256, 4) void class_kernel(
    const float* __restrict__ v_class,
    const int* __restrict__ step_ptr,
    float* __restrict__ out,
    float Bf)
{
    __shared__ float red[8];
    __shared__ bool amLast;
    const int c = blockIdx.x;
    const int t = threadIdx.x;       // dim index, 0..255

    float s = g_sums[c * DD + t];             // sums_c[t]
    float cnt = g_counts[c];

    float stepf = (float)(*step_ptr);
    float alpha = fminf(0.02f, stepf / (stepf + 50.0f));
    float oma = 1.0f - alpha;

    float invc = 1.0f / fmaxf(cnt, 1.0f);
    float bm = s * invc;

    float nb = block_sum256(bm * bm, red, t);
    float invb = 1.0f / fmaxf(sqrtf(nb), 1e-12f);

    float vc = v_class[c * DD + t];
    float u = oma * vc + alpha * bm * invb;

    float nu = block_sum256(u * u, red, t);
    float invu = 1.0f / fmaxf(sqrtf(nu), 1e-12f);

    float w = (cnt > 0.0f) ? u * invu : vc;
    out[1 + c * DD + t] = w;

    float dot = block_sum256(s * w, red, t);
    if (t == 0) g_dots[c] = dot;

    // re-zero this class's accumulator slice (replay-invariant state)
    g_sums[c * DD + t] = 0.0f;
    if (t == 0) g_counts[c] = 0.0f;

    // ---- fused loss: last CTA to finish sums g_dots ----
    if (t == 0) {
        __threadfence();
        amLast = (atomicAdd(&g_done, 1u) == CC - 1);
    }
    __syncthreads();
    if (amLast) {
        float v = (t < CC) ? g_dots[t] : 0.f;
        float tot = block_sum256(v, red, t);
        if (t == 0) {
            out[0] = 0.1f * (1.0f - tot / Bf);
            g_done = 0;              // reset for next graph replay
        }
    }
}

extern "C" void kernel_launch(void* const* d_in, const int* in_sizes, int n_in,
                              void* d_out, int out_size)
{
    const float* dirs    = (const float*)d_in[0];
    const float* v_class = (const float*)d_in[1];
    const int*   labels  = (const int*)d_in[2];
    const int*   step    = (const int*)d_in[3];
    int B = in_sizes[2];

    cudaFuncSetAttribute(accum_kernel,
                         cudaFuncAttributeMaxDynamicSharedMemorySize, SMEM_BYTES);

    accum_kernel<<<GRID1, T1, SMEM_BYTES>>>(dirs, labels, B);
    class_kernel<<<CC, 256>>>(v_class, step, (float*)d_out, (float)B);
}

// round 17
// speedup vs baseline: 1.6423x; 1.0249x over previous
#include <cuda_runtime.h>
#include <cstdint>

// PrototypeField: B=262144, D=256, C=128.
// out[0] = 0.1*(1 - mean cos_sim), out[1..32768] = new_v (C,D).
//
// Identity: sum_i <dirs_n_i, new_v[label_i]> = sum_c <sums_c, new_v_c>,
// so dirs is read exactly once (268 MB, HBM floor ~34us).
//
// accum_kernel (148 CTAs x 1024 thr):
//   phase A (match.any): each warp counts+scatters ONLY its own 56-row
//   chunk; cross-warp per-class exclusive scan gives deterministic,
//   class-sorted row lists for the whole CTA.
//   phase B: warps take EQUAL contiguous slices of the sorted list
//   (56+-1 rows -- no Poisson class imbalance; any warp can flush any
//   class because flushes are REDG atomicAdd float4 into g_sums).
//   Slices may end mid-class: the loop flushes at class boundaries and
//   an EPILOGUE flush (cend > e0) covers the pending partial class --
//   this was the R15 correctness bug.
//   Per-warp 6-slot x 1KB cp.async ring, 2 rows/iter, dual interleaved
//   5-shfl allreduces + MUFU.RSQ.
// class_kernel (128x256): per class, read g_sums/g_counts + EMA + renorm +
// write new_v + dot, then RE-ZERO its class slice (replay-invariant);
// last CTA computes the loss (fused, counter resets).

#define DD 256
#define CC 128
#define GRID1 148
#define T1 1024
#define NW (T1 / 32)          // 32 warps
#define CPW (CC / NW)         // 4 classes per warp (phase A only)
#define FULLM 0xFFFFFFFFu
#define DEPTH 6               // ring slots per warp (3 groups x 2 rows)
#define WSTRIDE 129           // padded woff row stride (bank-conflict-free)

// dynamic smem layout (bytes):
//   [0, 196608)           stage: 32 warps x 6 slots x 1024B
//   [196608, 213120)      woff   int[32*129] (counts -> offsets -> cursors)
//   [213120, 216704)      list   ushort[1792]
//   [216704, 217216)      ccount int[128]
//   [217216, 217732)      cbase  int[129]
#define OFF_STAGE  0
#define OFF_WOFF   196608
#define OFF_LIST   213120
#define OFF_CCOUNT 216704
#define OFF_CBASE  217216
#define SMEM_BYTES 217760

__device__ float g_sums[CC * DD];             // zero at load; re-zeroed by class_kernel
__device__ float g_counts[CC];                // zero at load; re-zeroed by class_kernel
__device__ float g_dots[CC];                  // fully overwritten each run
__device__ unsigned int g_done;               // 0; self-resetting counter

#define DOT8(p, q) ((p).x*(p).x + (p).y*(p).y + (p).z*(p).z + (p).w*(p).w \
                  + (q).x*(q).x + (q).y*(q).y + (q).z*(q).z + (q).w*(q).w)
#define AXPY4(acc, v, s) do { (acc).x += (v).x*(s); (acc).y += (v).y*(s); \
                              (acc).z += (v).z*(s); (acc).w += (v).w*(s); } while (0)

__device__ __forceinline__ void cp16(uint32_t dst, const void* src) {
    asm volatile("cp.async.cg.shared.global [%0], [%1], 16;\n"
                 :: "r"(dst), "l"(src) : "memory");
}

__device__ __forceinline__ float warp_sum(float v) {
    #pragma unroll
    for (int o = 16; o > 0; o >>= 1) v += __shfl_xor_sync(FULLM, v, o);
    return v;
}

__global__ __launch_bounds__(T1, 1) void accum_kernel(
    const float* __restrict__ dirs,
    const int* __restrict__ labels,
    int B)
{
    extern __shared__ char dynsmem[];
    int*            woff   = (int*)(dynsmem + OFF_WOFF);
    unsigned short* list   = (unsigned short*)(dynsmem + OFF_LIST);
    int*            ccount = (int*)(dynsmem + OFF_CCOUNT);
    int*            cbase  = (int*)(dynsmem + OFF_CBASE);

    const int tid  = threadIdx.x;
    const int wid  = tid >> 5;
    const int lane = tid & 31;
    const int base_c = wid * CPW;

    const int rows_per = (B + GRID1 - 1) / GRID1;   // 1772
    const int row0  = blockIdx.x * rows_per;
    const int nrows = min(rows_per, B - row0);
    if (nrows <= 0) return;

    // warp's contiguous row chunk (rpw <= 56, so exactly 2 sub-chunks of 32)
    const int rpw    = (nrows + NW - 1) / NW;
    const int wstart = wid * rpw;
    const int wend   = min(wstart + rpw, nrows);

    // ---- Phase A1: per-warp per-class counts via match.any ----
    for (int c = lane; c < CC; c += 32) woff[wid * WSTRIDE + c] = 0;
    __syncwarp();
    int labreg[2];
    #pragma unroll
    for (int ch = 0; ch < 2; ch++) {
        int r = wstart + ch * 32 + lane;
        int lab = (r < wend) ? labels[row0 + r] : -1;
        labreg[ch] = lab;
        unsigned m = __match_any_sync(FULLM, lab);
        unsigned below = (1u << lane) - 1u;
        if (lab >= 0 && __popc(m & below) == 0)      // leader of its group
            woff[wid * WSTRIDE + lab] += __popc(m);
        __syncwarp();
    }
    __syncthreads();

    // ---- Phase A2a: cross-warp exclusive scan per class ----
    #pragma unroll
    for (int k = 0; k < CPW; k++) {
        int c = base_c + k;
        int v = woff[lane * WSTRIDE + c];
        int x = v;
        #pragma unroll
        for (int o = 1; o < 32; o <<= 1) {
            int y = __shfl_up_sync(FULLM, x, o);
            if (lane >= o) x += y;
        }
        woff[lane * WSTRIDE + c] = x - v;            // exclusive within class
        if (lane == 31) ccount[c] = x;               // class total
    }
    __syncthreads();

    // ---- Phase A2b: exclusive prefix over class totals (warp 0) ----
    if (wid == 0) {
        int k0 = ccount[lane * 4], k1 = ccount[lane * 4 + 1];
        int k2 = ccount[lane * 4 + 2], k3 = ccount[lane * 4 + 3];
        int s = k0 + k1 + k2 + k3;
        int x = s;
        #pragma unroll
        for (int o = 1; o < 32; o <<= 1) {
            int y = __shfl_up_sync(FULLM, x, o);
            if (lane >= o) x += y;
        }
        int excl = x - s;
        cbase[lane * 4]     = excl;
        cbase[lane * 4 + 1] = excl + k0;
        cbase[lane * 4 + 2] = excl + k0 + k1;
        cbase[lane * 4 + 3] = excl + k0 + k1 + k2;
        if (lane == 31) cbase[CC] = excl + s;
    }
    __syncthreads();

    // woff[w][c] += cbase[c]  -> absolute write cursor per (warp, class)
    for (int i = tid; i < NW * CC; i += T1) {
        int w = i >> 7, c = i & (CC - 1);
        woff[w * WSTRIDE + c] += cbase[c];
    }
    __syncthreads();

    // ---- Phase A3: scatter own rows via match.any (deterministic) ----
    #pragma unroll
    for (int ch = 0; ch < 2; ch++) {
        int r = wstart + ch * 32 + lane;
        int lab = labreg[ch];
        unsigned m = __match_any_sync(FULLM, lab);
        unsigned below = (1u << lane) - 1u;
        int rank = __popc(m & below);
        int base = (lab >= 0) ? woff[wid * WSTRIDE + lab] : 0;
        __syncwarp();
        if (lab >= 0) {
            if (rank == 0) woff[wid * WSTRIDE + lab] = base + __popc(m);
            list[base + rank] = (unsigned short)r;
        }
        __syncwarp();
    }
    __syncthreads();

    // ---- flush per-CTA class counts (REDG, fire-and-forget) ----
    if (tid < CC && ccount[tid] > 0)
        atomicAdd(&g_counts[tid], (float)ccount[tid]);

    // ---- Phase B: EQUAL slices of the class-sorted list per warp ----
    // (any warp may flush any class: flushes are atomic)
    const int s0 = min(wid * rpw, nrows);
    const int e0 = min(s0 + rpw, nrows);
    if (s0 < e0) {
        const char* dbytes = (const char*)dirs + (long long)row0 * 1024;
        char* stage_w = dynsmem + OFF_STAGE + wid * (DEPTH * 1024);
        const uint32_t stage_base =
            (uint32_t)__cvta_generic_to_shared(stage_w) + (uint32_t)(lane * 16);
        const float4 z = make_float4(0.f, 0.f, 0.f, 0.f);

        // binary search: cls with cbase[cls] <= s0 < cbase[cls+1]
        int lo = 0, hi = CC - 1;
        while (lo < hi) {
            int mid = (lo + hi) >> 1;
            if (cbase[mid + 1] <= s0) lo = mid + 1; else hi = mid;
        }
        int cls = lo;
        int cend = cbase[cls + 1];

        // prologue: 3 groups of up-to-2 rows into slots 0..5
        #pragma unroll
        for (int g = 0; g < 3; g++) {
            int r0 = s0 + 2 * g, r1 = r0 + 1;
            if (r0 < e0) {
                const char* src = dbytes + (long long)list[r0] * 1024 + lane * 16;
                uint32_t dst = stage_base + (2 * g) * 1024;
                cp16(dst, src); cp16(dst + 512, src + 512);
            }
            if (r1 < e0) {
                const char* src = dbytes + (long long)list[r1] * 1024 + lane * 16;
                uint32_t dst = stage_base + (2 * g + 1) * 1024;
                cp16(dst, src); cp16(dst + 512, src + 512);
            }
            asm volatile("cp.async.commit_group;\n" ::: "memory");
        }

        float4 AL = z, AH = z;
        int slotA = 0;                       // cycles 0,2,4

        for (int i = s0; i < e0; i += 2) {
            asm volatile("cp.async.wait_group 2;\n" ::: "memory");

            const float4* spA = (const float4*)(stage_w + slotA * 1024) + lane;
            const float4* spB = (const float4*)(stage_w + (slotA + 1) * 1024) + lane;
            float4 a0 = spA[0], a1 = spA[32];
            float4 b0 = spB[0], b1 = spB[32];   // garbage if i+1>=e0 (unused)
            const bool two = (i + 1 < e0);

            // prefetch rows i+6, i+7 into the slots just consumed
            if (i + 6 < e0) {
                const char* src = dbytes + (long long)list[i + 6] * 1024 + lane * 16;
                uint32_t dst = stage_base + slotA * 1024;
                cp16(dst, src); cp16(dst + 512, src + 512);
            }
            if (i + 7 < e0) {
                const char* src = dbytes + (long long)list[i + 7] * 1024 + lane * 16;
                uint32_t dst = stage_base + (slotA + 1) * 1024;
                cp16(dst, src); cp16(dst + 512, src + 512);
            }
            asm volatile("cp.async.commit_group;\n" ::: "memory");

            // dual interleaved allreduce (hides shfl latency)
            float sa = DOT8(a0, a1);
            float sb = DOT8(b0, b1);
            #pragma unroll
            for (int o = 16; o > 0; o >>= 1) {
                sa += __shfl_xor_sync(FULLM, sa, o);
                sb += __shfl_xor_sync(FULLM, sb, o);
            }

            // rsqrt(max(s,1e-24)) == 1/max(sqrt(s),1e-12) for all s
            float inva = rsqrtf(fmaxf(sa, 1e-24f));
            AXPY4(AL, a0, inva);
            AXPY4(AH, a1, inva);

            if (i + 1 >= cend) {             // row i last of cls within slice
                float* sp = g_sums + cls * DD + (lane << 2);
                atomicAdd((float4*)sp, AL);
                atomicAdd((float4*)(sp + 128), AH);
                AL = z; AH = z;
                if (i + 1 < e0) {
                    cls++;
                    while (i + 1 >= cbase[cls + 1]) cls++;
                    cend = cbase[cls + 1];
                }
            }

            if (two) {
                float invb = rsqrtf(fmaxf(sb, 1e-24f));
                AXPY4(AL, b0, invb);
                AXPY4(AH, b1, invb);

                if (i + 2 >= cend) {         // row i+1 last of cls within slice
                    float* sp = g_sums + cls * DD + (lane << 2);
                    atomicAdd((float4*)sp, AL);
                    atomicAdd((float4*)(sp + 128), AH);
                    AL = z; AH = z;
                    if (i + 2 < e0) {
                        cls++;
                        while (i + 2 >= cbase[cls + 1]) cls++;
                        cend = cbase[cls + 1];
                    }
                }
            }

            slotA += 2;
            if (slotA == DEPTH) slotA = 0;
        }

        // EPILOGUE FLUSH (the R15 bug fix): slice ended mid-class, so the
        // in-loop boundary condition never fired for the last partial class.
        if (cend > e0) {
            float* sp = g_sums + cls * DD + (lane << 2);
            atomicAdd((float4*)sp, AL);
            atomicAdd((float4*)(sp + 128), AH);
        }
    }
}

__device__ __forceinline__ float block_sum256(float v, volatile float* red, int t)
{
    v = warp_sum(v);
    __syncthreads();                 // protect red from previous use
    if ((t & 31) == 0) red[t >> 5] = v;
    __syncthreads();
    return red[0] + red[1] + red[2] + red[3] + red[4] + red[5] + red[6] + red[7];
}

__global__ __launch_bounds__(256, 4) void class_kernel(
    const float* __restrict__ v_class,
    const int* __restrict__ step_ptr,
    float* __restrict__ out,
    float Bf)
{
    __shared__ float red[8];
    __shared__ bool amLast;
    const int c = blockIdx.x;
    const int t = threadIdx.x;       // dim index, 0..255

    float s = g_sums[c * DD + t];             // sums_c[t]
    float cnt = g_counts[c];

    float stepf = (float)(*step_ptr);
    float alpha = fminf(0.02f, stepf / (stepf + 50.0f));
    float oma = 1.0f - alpha;

    float invc = 1.0f / fmaxf(cnt, 1.0f);
    float bm = s * invc;

    float nb = block_sum256(bm * bm, red, t);
    float invb = 1.0f / fmaxf(sqrtf(nb), 1e-12f);

    float vc = v_class[c * DD + t];
    float u = oma * vc + alpha * bm * invb;

    float nu = block_sum256(u * u, red, t);
    float invu = 1.0f / fmaxf(sqrtf(nu), 1e-12f);

    float w = (cnt > 0.0f) ? u * invu : vc;
    out[1 + c * DD + t] = w;

    float dot = block_sum256(s * w, red, t);
    if (t == 0) g_dots[c] = dot;

    // re-zero this class's accumulator slice (replay-invariant state)
    g_sums[c * DD + t] = 0.0f;
    if (t == 0) g_counts[c] = 0.0f;

    // ---- fused loss: last CTA to finish sums g_dots ----
    if (t == 0) {
        __threadfence();
        amLast = (atomicAdd(&g_done, 1u) == CC - 1);
    }
    __syncthreads();
    if (amLast) {
        float v = (t < CC) ? g_dots[t] : 0.f;
        float tot = block_sum256(v, red, t);
        if (t == 0) {
            out[0] = 0.1f * (1.0f - tot / Bf);
            g_done = 0;              // reset for next graph replay
        }
    }
}

extern "C" void kernel_launch(void* const* d_in, const int* in_sizes, int n_in,
                              void* d_out, int out_size)
{
    const float* dirs    = (const float*)d_in[0];
    const float* v_class = (const float*)d_in[1];
    const int*   labels  = (const int*)d_in[2];
    const int*   step    = (const int*)d_in[3];
    int B = in_sizes[2];

    cudaFuncSetAttribute(accum_kernel,
                         cudaFuncAttributeMaxDynamicSharedMemorySize, SMEM_BYTES);

    accum_kernel<<<GRID1, T1, SMEM_BYTES>>>(dirs, labels, B);
    class_kernel<<<CC, 256>>>(v_class, step, (float*)d_out, (float)B);
}